// round 1
// baseline (speedup 1.0000x reference)
#include <cuda_runtime.h>

#define Tn  512
#define Bn  1024
#define Sn  64
#define An  16
#define Hn  128
#define TBn (Tn*Bn)

// Scratch (allocation-free rule: __device__ globals)
__device__ float g_gx[(size_t)TBn * 384];      // x-side gate preactivations [T*B, 3H]
__device__ float g_hidden[(size_t)TBn * Hn];   // GRU hidden states [T*B, H]

// ---------------------------------------------------------------------------
// Kernel 1: fused encoder  x[32-row tile] -> h1 -> h2 -> gx
// 512 threads, 32 rows/block. Micro-tile 4 rows x {2,2,6} cols per thread.
// Weights staged in smem (padded strides for conflict-free access),
// activations broadcast from smem.
// ---------------------------------------------------------------------------
__global__ void __launch_bounds__(512, 2) encoder_kernel(
    const float* __restrict__ x,
    const float* __restrict__ W1, const float* __restrict__ b1,
    const float* __restrict__ W2, const float* __restrict__ b2,
    const float* __restrict__ Wih, const float* __restrict__ bih)
{
    extern __shared__ float sm[];
    const int OFF_XS = 64 * 129;          // 8256  (xs lives inside phase-A only)
    const int OFF_H1 = 128 * 129;         // 16512
    const int OFF_H2 = OFF_H1 + 32 * 129; // 20640

    int tid = threadIdx.x;
    int cg  = tid & 63;       // column group 0..63
    int rg  = tid >> 6;       // row group 0..7
    int r0  = rg << 2;        // rows r0..r0+3
    int row_base = blockIdx.x * 32;

    // ---- Phase A: h1 = relu(x @ W1^T + b1)  (K=64, N=128) ----
    for (int idx = tid; idx < 32 * 64; idx += 512) {
        int r = idx >> 6, k = idx & 63;
        sm[OFF_XS + r * 65 + k] = x[(row_base + r) * 64 + k];
    }
    for (int idx = tid; idx < 128 * 64; idx += 512) {
        int k = idx & 63, j = idx >> 6;
        sm[k * 129 + j] = W1[j * 64 + k];      // W1T[k][j]
    }
    __syncthreads();
    {
        float a0[4], a1[4];
        float bj0 = b1[cg], bj1 = b1[cg + 64];
        #pragma unroll
        for (int i = 0; i < 4; i++) { a0[i] = bj0; a1[i] = bj1; }
        #pragma unroll 4
        for (int k = 0; k < 64; k++) {
            float w0 = sm[k * 129 + cg];
            float w1 = sm[k * 129 + cg + 64];
            #pragma unroll
            for (int i = 0; i < 4; i++) {
                float hv = sm[OFF_XS + (r0 + i) * 65 + k];   // warp broadcast
                a0[i] += hv * w0; a1[i] += hv * w1;
            }
        }
        __syncthreads();   // all W1T/xs reads done before overwrite below
        #pragma unroll
        for (int i = 0; i < 4; i++) {
            sm[OFF_H1 + (r0 + i) * 129 + cg]      = fmaxf(a0[i], 0.f);
            sm[OFF_H1 + (r0 + i) * 129 + cg + 64] = fmaxf(a1[i], 0.f);
        }
    }
    for (int idx = tid; idx < 128 * 128; idx += 512) {
        int k = idx & 127, j = idx >> 7;
        sm[k * 129 + j] = W2[j * 128 + k];     // W2T[k][j]
    }
    __syncthreads();

    // ---- Phase B: h2 = relu(h1 @ W2^T + b2)  (K=128, N=128) ----
    {
        float a0[4], a1[4];
        float bj0 = b2[cg], bj1 = b2[cg + 64];
        #pragma unroll
        for (int i = 0; i < 4; i++) { a0[i] = bj0; a1[i] = bj1; }
        #pragma unroll 4
        for (int k = 0; k < 128; k++) {
            float w0 = sm[k * 129 + cg];
            float w1 = sm[k * 129 + cg + 64];
            #pragma unroll
            for (int i = 0; i < 4; i++) {
                float hv = sm[OFF_H1 + (r0 + i) * 129 + k];
                a0[i] += hv * w0; a1[i] += hv * w1;
            }
        }
        #pragma unroll
        for (int i = 0; i < 4; i++) {
            sm[OFF_H2 + (r0 + i) * 129 + cg]      = fmaxf(a0[i], 0.f);
            sm[OFF_H2 + (r0 + i) * 129 + cg + 64] = fmaxf(a1[i], 0.f);
        }
    }

    // ---- Phase C: gx = h2 @ W_ih^T + b_ih  (K=128, N=384), K streamed in 4 chunks ----
    float acc[4][6];
    #pragma unroll
    for (int m = 0; m < 6; m++) {
        float bj = bih[cg + (m << 6)];
        #pragma unroll
        for (int i = 0; i < 4; i++) acc[i][m] = bj;
    }
    for (int c4 = 0; c4 < 4; c4++) {
        __syncthreads();  // prior reads of W region / h2 writes visible
        for (int idx = tid; idx < 32 * 384; idx += 512) {
            int kl = idx & 31, j = idx >> 5;
            sm[kl * 385 + j] = Wih[j * 128 + c4 * 32 + kl];   // WihT[kl][j]
        }
        __syncthreads();
        #pragma unroll 2
        for (int kl = 0; kl < 32; kl++) {
            int k = c4 * 32 + kl;
            float hv[4];
            #pragma unroll
            for (int i = 0; i < 4; i++) hv[i] = sm[OFF_H2 + (r0 + i) * 129 + k];
            #pragma unroll
            for (int m = 0; m < 6; m++) {
                float w = sm[kl * 385 + cg + (m << 6)];
                #pragma unroll
                for (int i = 0; i < 4; i++) acc[i][m] += hv[i] * w;
            }
        }
    }
    #pragma unroll
    for (int i = 0; i < 4; i++) {
        int row = row_base + r0 + i;
        #pragma unroll
        for (int m = 0; m < 6; m++)
            g_gx[row * 384 + cg + (m << 6)] = acc[i][m];
    }
}

// ---------------------------------------------------------------------------
// Kernel 2: GRU scan. 128 blocks x 8 batch rows, 256 threads.
// W_hh resident in smem (padded). Thread = column c, owns gate cols
// {c, c+128, c+256} for 4 rows -> gh never leaves registers.
// done-mask folded into h store; next-step gx prefetched.
// ---------------------------------------------------------------------------
__device__ __forceinline__ float sigmoidf_(float v) {
    float e = __expf(-v);
    return __fdividef(1.f, 1.f + e);
}

__global__ void __launch_bounds__(256, 1) scan_kernel(
    const float* __restrict__ done, const float* __restrict__ gru0,
    const float* __restrict__ Whh, const float* __restrict__ bhh,
    float* __restrict__ out)
{
    extern __shared__ float sm[];
    const int OFF_H = 128 * 385;   // 49280 floats; WhhT[k][j] in [0, OFF_H)
    int tid = threadIdx.x;
    int b0  = blockIdx.x << 3;     // 8 batch rows per block

    for (int idx = tid; idx < 384 * 128; idx += 256) {
        int k = idx & 127, j = idx >> 7;
        sm[k * 385 + j] = Whh[j * 128 + k];
    }
    for (int idx = tid; idx < 8 * 128; idx += 256) {
        int r = idx >> 7, k = idx & 127;
        float m = 1.f - done[b0 + r];                 // mask for t=0
        sm[OFF_H + r * 129 + k] = gru0[(b0 + r) * 128 + k] * m;
    }
    __syncthreads();

    int c  = tid & 127;
    int rg = (tid >> 7) << 2;   // 0 or 4
    float br = bhh[c], bz = bhh[c + 128], bnv = bhh[c + 256];

    float gxc[4][3];
    #pragma unroll
    for (int i = 0; i < 4; i++) {
        int row = b0 + rg + i;   // t = 0
        #pragma unroll
        for (int m = 0; m < 3; m++) gxc[i][m] = g_gx[row * 384 + c + (m << 7)];
    }

    for (int t = 0; t < Tn; t++) {
        int base = t * Bn + b0;
        float ar[4], az[4], anv[4], gn[4], hold[4];
        #pragma unroll
        for (int i = 0; i < 4; i++) {
            ar[i]  = br + gxc[i][0];
            az[i]  = bz + gxc[i][1];
            gn[i]  = gxc[i][2];
            anv[i] = bnv;
            hold[i] = sm[OFF_H + (rg + i) * 129 + c];
        }
        // prefetch next step's gx while the matmul runs
        int tnext = (t + 1 < Tn) ? (t + 1) : t;
        #pragma unroll
        for (int i = 0; i < 4; i++) {
            int row = tnext * Bn + b0 + rg + i;
            #pragma unroll
            for (int m = 0; m < 3; m++) gxc[i][m] = g_gx[row * 384 + c + (m << 7)];
        }
        // gh = h @ Whh^T : dot over k=0..127
        #pragma unroll 2
        for (int k = 0; k < 128; k++) {
            float wr = sm[k * 385 + c];
            float wz = sm[k * 385 + c + 128];
            float wn = sm[k * 385 + c + 256];
            #pragma unroll
            for (int i = 0; i < 4; i++) {
                float hv = sm[OFF_H + (rg + i) * 129 + k];   // warp broadcast
                ar[i]  += hv * wr;
                az[i]  += hv * wz;
                anv[i] += hv * wn;
            }
        }
        __syncthreads();   // all h_s reads complete before overwrite
        #pragma unroll
        for (int i = 0; i < 4; i++) {
            float r = sigmoidf_(ar[i]);
            float z = sigmoidf_(az[i]);
            float pn = gn[i] + r * anv[i];
            float e2 = __expf(-2.f * pn);
            float n  = (1.f - e2) * __fdividef(1.f, 1.f + e2);   // tanh(pn)
            float hnew = (1.f - z) * n + z * hold[i];
            int row = base + rg + i;
            g_hidden[row * Hn + c] = hnew;
            float dn = (t + 1 < Tn) ? done[(t + 1) * Bn + b0 + rg + i] : 0.f;
            sm[OFF_H + (rg + i) * 129 + c] = hnew * (1.f - dn);  // next-step mask folded in
            if (t == Tn - 1)
                out[TBn * 3 + (b0 + rg + i) * Hn + c] = hnew;    // h_last
        }
        __syncthreads();
    }
}

// ---------------------------------------------------------------------------
// Kernel 3: heads. 256 rows/block, thread-per-row; h rows + Wa/Wc in smem.
// ---------------------------------------------------------------------------
__global__ void __launch_bounds__(256, 1) heads_kernel(
    const int* __restrict__ action,
    const float* __restrict__ Wa, const float* __restrict__ ba,
    const float* __restrict__ Wc, const float* __restrict__ bc,
    float* __restrict__ out)
{
    extern __shared__ float sm[];
    const int OFF_WA = 256 * 129;           // 33024
    const int OFF_WC = OFF_WA + 16 * 128;   // 35072
    int tid  = threadIdx.x;
    int base = blockIdx.x << 8;

    for (int idx = tid; idx < 256 * 128; idx += 256) {
        int r = idx >> 7, k = idx & 127;
        sm[r * 129 + k] = g_hidden[(base + r) * 128 + k];
    }
    for (int idx = tid; idx < 16 * 128; idx += 256) sm[OFF_WA + idx] = Wa[idx];
    if (tid < 128) sm[OFF_WC + tid] = Wc[tid];
    __syncthreads();

    float l[16];
    #pragma unroll
    for (int j = 0; j < 16; j++) l[j] = ba[j];
    float v = bc[0];
    const float* hrow = &sm[tid * 129];
    #pragma unroll 4
    for (int k = 0; k < 128; k++) {
        float hv = hrow[k];
        #pragma unroll
        for (int j = 0; j < 16; j++) l[j] += sm[OFF_WA + j * 128 + k] * hv;
        v += sm[OFF_WC + k] * hv;
    }
    float mx = l[0];
    #pragma unroll
    for (int j = 1; j < 16; j++) mx = fmaxf(mx, l[j]);
    float se = 0.f, pl = 0.f;
    #pragma unroll
    for (int j = 0; j < 16; j++) {
        float e = __expf(l[j] - mx);
        se += e; pl += e * l[j];
    }
    float lse = mx + __logf(se);
    int row = base + tid;
    int a = action[row];
    float la = 0.f;
    #pragma unroll
    for (int j = 0; j < 16; j++) la = (a == j) ? l[j] : la;
    out[row * 3 + 0] = la - lse;        // log_prob
    out[row * 3 + 1] = lse - pl / se;   // entropy
    out[row * 3 + 2] = v;               // value
}

// ---------------------------------------------------------------------------
extern "C" void kernel_launch(void* const* d_in, const int* in_sizes, int n_in,
                              void* d_out, int out_size)
{
    const float* x    = (const float*)d_in[0];
    const float* done = (const float*)d_in[1];
    const int*   act  = (const int*)  d_in[2];
    const float* gru  = (const float*)d_in[3];
    const float* W1   = (const float*)d_in[4];
    const float* b1   = (const float*)d_in[5];
    const float* W2   = (const float*)d_in[6];
    const float* b2   = (const float*)d_in[7];
    const float* Wih  = (const float*)d_in[8];
    const float* bih  = (const float*)d_in[9];
    const float* Whh  = (const float*)d_in[10];
    const float* bhh  = (const float*)d_in[11];
    const float* Wa   = (const float*)d_in[12];
    const float* ba   = (const float*)d_in[13];
    const float* Wc   = (const float*)d_in[14];
    const float* bc   = (const float*)d_in[15];
    float* out = (float*)d_out;

    size_t enc_smem  = (size_t)(128 * 129 + 32 * 129 + 32 * 129) * sizeof(float); //  99072 B
    size_t scan_smem = (size_t)(128 * 385 + 8 * 129) * sizeof(float);             // 201248 B
    size_t head_smem = (size_t)(256 * 129 + 16 * 128 + 128) * sizeof(float);      // 140800 B

    cudaFuncSetAttribute(encoder_kernel, cudaFuncAttributeMaxDynamicSharedMemorySize, (int)enc_smem);
    cudaFuncSetAttribute(scan_kernel,    cudaFuncAttributeMaxDynamicSharedMemorySize, (int)scan_smem);
    cudaFuncSetAttribute(heads_kernel,   cudaFuncAttributeMaxDynamicSharedMemorySize, (int)head_smem);

    encoder_kernel<<<TBn / 32, 512, enc_smem>>>(x, W1, b1, W2, b2, Wih, bih);
    scan_kernel<<<128, 256, scan_smem>>>(done, gru, Whh, bhh, out);
    heads_kernel<<<TBn / 256, 256, head_smem>>>(act, Wa, ba, Wc, bc, out);
}